// round 2
// baseline (speedup 1.0000x reference)
#include <cuda_runtime.h>
#include <math.h>

#define PIf 3.14159265358979323846f
#define FLOOR_Zf (-1.6f)

// Select one of 4 register-resident scalars by dynamic index via SEL chain
// (keeps everything in registers; no local-memory spill from dynamic indexing).
__device__ __forceinline__ float sel4(int k, float a0, float a1, float a2, float a3) {
    float r = (k == 1) ? a1 : a0;
    r = (k == 2) ? a2 : r;
    r = (k == 3) ? a3 : r;
    return r;
}

// det of 3x3 with columns (ax,ay,1),(bx,by,1),(cx,cy,1)  (= 2x signed triangle area)
__device__ __forceinline__ float det3(float ax, float ay, float bx, float by, float cx, float cy) {
    return ax * (by - cy) + bx * (cy - ay) + cx * (ay - by);
}

__global__ void __launch_bounds__(256)
cuboid_kernel(const float4* __restrict__ topc,   // (B,4,2) as 2x float4
              const float4* __restrict__ botc,   // (B,4,2) as 2x float4
              const float*  __restrict__ cax,    // (1,4,2) = 8 floats
              float* __restrict__ out_top,       // (B,4,3)
              float* __restrict__ out_bot,       // (B,4,3)
              int B)
{
    int b = blockIdx.x * blockDim.x + threadIdx.x;
    if (b >= B) return;

    float4 bA = botc[2 * b], bB = botc[2 * b + 1];
    float4 tA = topc[2 * b], tB = topc[2 * b + 1];

    float bu[4] = {bA.x, bA.z, bB.x, bB.z};
    float bv[4] = {bA.y, bA.w, bB.y, bB.w};
    float tv[4] = {tA.y, tA.w, tB.y, tB.w};

    // ---- floor_xy -------------------------------------------------------
    float px[4], py[4];
#pragma unroll
    for (int i = 0; i < 4; i++) {
        float u = bu[i] * PIf;
        float v = bv[i] * (-0.5f * PIf);
        float c = FLOOR_Zf / tanf(v);
        px[i] = c * sinf(u);
        py[i] = -c * cosf(u);
    }

    // ---- half-scales (scale = [a_y, a_x] / 2) ---------------------------
    float dx, dy;
    dx = px[0] - px[1]; dy = py[0] - py[1]; float d01 = sqrtf(dx * dx + dy * dy);
    dx = px[1] - px[2]; dy = py[1] - py[2]; float d12 = sqrtf(dx * dx + dy * dy);
    dx = px[2] - px[3]; dy = py[2] - py[3]; float d23 = sqrtf(dx * dx + dy * dy);
    dx = px[3] - px[0]; dy = py[3] - py[0]; float d30 = sqrtf(dx * dx + dy * dy);
    float sc_x = 0.25f * (d12 + d30);   // a_y/2  -> multiplies x coord
    float sc_y = 0.25f * (d01 + d23);   // a_x/2  -> multiplies y coord

    // ---- centroid -------------------------------------------------------
    float cx = 0.25f * (px[0] + px[1] + px[2] + px[3]);
    float cy = 0.25f * (py[0] + py[1] + py[2] + py[3]);

    // ---- ceiling z ------------------------------------------------------
    float cz = 0.0f;
#pragma unroll
    for (int i = 0; i < 4; i++) {
        float cn = sqrtf(px[i] * px[i] + py[i] * py[i]);
        cz += cn * tanf(tv[i] * (-0.5f * PIf));
    }
    cz *= 0.25f;

    // ---- centered points + angle argsort (stable) -----------------------
    float fxx[4], fxy[4], ang[4];
#pragma unroll
    for (int i = 0; i < 4; i++) {
        fxx[i] = px[i] - cx;
        fxy[i] = py[i] - cy;
        ang[i] = atan2f(fxx[i], fxy[i] + 1e-12f);
    }
    int idx[4] = {0, 1, 2, 3};
    // stable bubble sort (adjacent swaps only, strict >)
#pragma unroll
    for (int pass = 0; pass < 3; pass++) {
#pragma unroll
        for (int j = 0; j < 3 - pass; j++) {
            float aj = sel4(0, ang[j], 0, 0, 0); // (static index; just use ang[j])
            aj = ang[j];
            if (ang[j] > ang[j + 1]) {
                float ta = ang[j]; ang[j] = ang[j + 1]; ang[j + 1] = ta;
                int ti = idx[j]; idx[j] = idx[j + 1]; idx[j + 1] = ti;
            }
            (void)aj;
        }
    }

    // ---- destination square corners: axes[i] = cuboid_axes[idx[i]] ------
    float ddx[4], ddy[4];
#pragma unroll
    for (int i = 0; i < 4; i++) {
        int k = idx[i];
        ddx[i] = __ldg(&cax[2 * k]);
        ddy[i] = __ldg(&cax[2 * k + 1]);
    }

    // ---- homography H: fx -> axes, projective-basis closed form ---------
    // src Cramer coefficients (basis = pts 0,1,2; fourth = pt 3); overall scale free
    float s0 = det3(fxx[3], fxy[3], fxx[1], fxy[1], fxx[2], fxy[2]);
    float s1 = det3(fxx[0], fxy[0], fxx[3], fxy[3], fxx[2], fxy[2]);
    float s2 = det3(fxx[0], fxy[0], fxx[1], fxy[1], fxx[3], fxy[3]);
    // dst Cramer coefficients
    float t0 = det3(ddx[3], ddy[3], ddx[1], ddy[1], ddx[2], ddy[2]);
    float t1 = det3(ddx[0], ddy[0], ddx[3], ddy[3], ddx[2], ddy[2]);
    float t2 = det3(ddx[0], ddy[0], ddx[1], ddy[1], ddx[3], ddy[3]);

    // adj(H_src): rows are cross products of H_src columns Cj = sj*(xj,yj,1)
    // cross((x1,y1,1),(x2,y2,1)) = (y1-y2, x2-x1, x1*y2-x2*y1)
    float a0 = s1 * s2 * (fxy[1] - fxy[2]);
    float b0 = s1 * s2 * (fxx[2] - fxx[1]);
    float c0 = s1 * s2 * (fxx[1] * fxy[2] - fxx[2] * fxy[1]);
    float a1 = s2 * s0 * (fxy[2] - fxy[0]);
    float b1 = s2 * s0 * (fxx[0] - fxx[2]);
    float c1 = s2 * s0 * (fxx[2] * fxy[0] - fxx[0] * fxy[2]);
    float a2 = s0 * s1 * (fxy[0] - fxy[1]);
    float b2 = s0 * s1 * (fxx[1] - fxx[0]);
    float c2 = s0 * s1 * (fxx[0] * fxy[1] - fxx[1] * fxy[0]);

    // H = H_dst * adj(H_src); H_dst columns Dj = tj*(dxj,dyj,1)
    float w0 = t0 * ddx[0], w1 = t1 * ddx[1], w2 = t2 * ddx[2];
    float H00 = w0 * a0 + w1 * a1 + w2 * a2;
    float H01 = w0 * b0 + w1 * b1 + w2 * b2;
    float H02 = w0 * c0 + w1 * c1 + w2 * c2;
    w0 = t0 * ddy[0]; w1 = t1 * ddy[1]; w2 = t2 * ddy[2];
    float H10 = w0 * a0 + w1 * a1 + w2 * a2;
    float H11 = w0 * b0 + w1 * b1 + w2 * b2;
    float H12 = w0 * c0 + w1 * c1 + w2 * c2;
    float H20 = t0 * a0 + t1 * a1 + t2 * a2;
    float H21 = t0 * b0 + t1 * b1 + t2 * b2;
    float H22 = t0 * c0 + t1 * c1 + t2 * c2;

    // ---- apply H, rescale, re-center ------------------------------------
    float rx[4], ry[4];
#pragma unroll
    for (int i = 0; i < 4; i++) {
        float wz = H20 * fxx[i] + H21 * fxy[i] + H22;
        float inv = 1.0f / wz;
        float X = (H00 * fxx[i] + H01 * fxy[i] + H02) * inv;
        float Y = (H10 * fxx[i] + H11 * fxy[i] + H12) * inv;
        rx[i] = X * sc_x + cx;
        ry[i] = Y * sc_y + cy;
    }

    // ---- Procrustes (closed-form 2x2 Kabsch) ----------------------------
    // points2 = floor_xy permuted by idx; both centered on rect centroid c1
    float rcx = 0.25f * (rx[0] + rx[1] + rx[2] + rx[3]);
    float rcy = 0.25f * (ry[0] + ry[1] + ry[2] + ry[3]);

    float K00 = 0.f, K01 = 0.f, K10 = 0.f, K11 = 0.f, var = 0.f;
#pragma unroll
    for (int i = 0; i < 4; i++) {
        float c1x = rx[i] - rcx;
        float c1y = ry[i] - rcy;
        int k = idx[i];
        float ox = sel4(k, px[0], px[1], px[2], px[3]);
        float oy = sel4(k, py[0], py[1], py[2], py[3]);
        float c2x = ox - rcx;
        float c2y = oy - rcy;
        var += c1x * c1x + c1y * c1y;
        K00 += c1x * c2x;
        K01 += c1x * c2y;
        K10 += c1y * c2x;
        K11 += c1y * c2y;
    }
    float aa = K00 + K11;
    float bb = K01 - K10;
    float rr = sqrtf(aa * aa + bb * bb);
    float inv_r = 1.0f / rr;
    float cth = aa * inv_r;
    float sth = bb * inv_r;
    float scl = rr / var;

    // rect' = c1 + scl * R * (rect - c1),  R = [[c,-s],[s,c]]
    float Rx[4], Ry[4];
#pragma unroll
    for (int i = 0; i < 4; i++) {
        float vx = rx[i] - rcx;
        float vy = ry[i] - rcy;
        Rx[i] = rcx + scl * (cth * vx - sth * vy);
        Ry[i] = rcy + scl * (sth * vx + cth * vy);
    }

    // ---- write outputs (12 floats each = 3x float4) ---------------------
    float4* ot = reinterpret_cast<float4*>(out_top) + (size_t)b * 3;
    float4* ob = reinterpret_cast<float4*>(out_bot) + (size_t)b * 3;
    ot[0] = make_float4(Rx[0], Ry[0], cz, Rx[1]);
    ot[1] = make_float4(Ry[1], cz, Rx[2], Ry[2]);
    ot[2] = make_float4(cz, Rx[3], Ry[3], cz);
    ob[0] = make_float4(Rx[0], Ry[0], FLOOR_Zf, Rx[1]);
    ob[1] = make_float4(Ry[1], FLOOR_Zf, Rx[2], Ry[2]);
    ob[2] = make_float4(FLOOR_Zf, Rx[3], Ry[3], FLOOR_Zf);
}

extern "C" void kernel_launch(void* const* d_in, const int* in_sizes, int n_in,
                              void* d_out, int out_size)
{
    int B = in_sizes[0] / 8;  // top_corners is (B,4,2)
    const float4* topc = (const float4*)d_in[0];
    const float4* botc = (const float4*)d_in[1];
    const float*  cax  = (const float*)d_in[2];
    float* out_top = (float*)d_out;
    float* out_bot = out_top + (size_t)B * 12;

    int threads = 256;
    int blocks = (B + threads - 1) / threads;
    cuboid_kernel<<<blocks, threads>>>(topc, botc, cax, out_top, out_bot, B);
}

// round 3
// speedup vs baseline: 1.3361x; 1.3361x over previous
#include <cuda_runtime.h>
#include <math.h>

#define PIf 3.14159265358979323846f
#define FLOOR_Zf (-1.6f)

// Select one of 4 register-resident scalars by dynamic index via SEL chain.
__device__ __forceinline__ float sel4(int k, float a0, float a1, float a2, float a3) {
    float r = (k == 1) ? a1 : a0;
    r = (k == 2) ? a2 : r;
    r = (k == 3) ? a3 : r;
    return r;
}

// det of 3x3 with columns (ax,ay,1),(bx,by,1),(cx,cy,1)
__device__ __forceinline__ float det3(float ax, float ay, float bx, float by, float cx, float cy) {
    return ax * (by - cy) + bx * (cy - ay) + cx * (ay - by);
}

// fast sqrt via MUFU.RSQ (args here are always > 0)
__device__ __forceinline__ float fsqrt_fast(float x) {
    return x * rsqrtf(x);
}

// Order-equivalent to atan2f(a_i,b_i) < atan2f(a_j,b_j).
// atan2f(a,b) = angle of vector (b,a) in (-pi, pi].
// Negative-angle half (a<0) sorts first; within a half-plane,
// cross((b_i,a_i),(b_j,a_j)) = b_i*a_j - a_i*b_j > 0  <=>  theta_i < theta_j.
__device__ __forceinline__ bool angLess(float ai, float bi, float aj, float bj) {
    bool hi = ai < 0.0f, hj = aj < 0.0f;
    if (hi != hj) return hi;
    return (bi * aj - ai * bj) > 0.0f;
}

__global__ void __launch_bounds__(256)
cuboid_kernel(const float4* __restrict__ topc,   // (B,4,2) as 2x float4
              const float4* __restrict__ botc,   // (B,4,2) as 2x float4
              const float*  __restrict__ cax,    // (1,4,2) = 8 floats
              float* __restrict__ out_top,       // (B,4,3)
              float* __restrict__ out_bot,       // (B,4,3)
              int B)
{
    int b = blockIdx.x * blockDim.x + threadIdx.x;
    if (b >= B) return;

    float4 bA = botc[2 * b], bB = botc[2 * b + 1];
    float4 tA = topc[2 * b], tB = topc[2 * b + 1];

    float bu[4] = {bA.x, bA.z, bB.x, bB.z};
    float bv[4] = {bA.y, bA.w, bB.y, bB.w};
    float tv[4] = {tA.y, tA.w, tB.y, tB.w};

    // ---- floor_xy: c = FLOOR_Z / tan(v);  p = (c*sin(u), -c*cos(u)) -----
    float px[4], py[4];
#pragma unroll
    for (int i = 0; i < 4; i++) {
        float u = bu[i] * PIf;
        float v = bv[i] * (-0.5f * PIf);
        float sv = __sinf(v), cv = __cosf(v);
        float c = __fdividef(FLOOR_Zf * cv, sv);
        float su, cu;
        __sincosf(u, &su, &cu);
        px[i] = c * su;
        py[i] = -c * cu;
    }

    // ---- half-scales (scale = [a_y, a_x] / 2) ---------------------------
    float dx, dy;
    dx = px[0] - px[1]; dy = py[0] - py[1]; float d01 = fsqrt_fast(dx * dx + dy * dy);
    dx = px[1] - px[2]; dy = py[1] - py[2]; float d12 = fsqrt_fast(dx * dx + dy * dy);
    dx = px[2] - px[3]; dy = py[2] - py[3]; float d23 = fsqrt_fast(dx * dx + dy * dy);
    dx = px[3] - px[0]; dy = py[3] - py[0]; float d30 = fsqrt_fast(dx * dx + dy * dy);
    float sc_x = 0.25f * (d12 + d30);   // a_y/2 -> multiplies x coord
    float sc_y = 0.25f * (d01 + d23);   // a_x/2 -> multiplies y coord

    // ---- centroid -------------------------------------------------------
    float cx = 0.25f * (px[0] + px[1] + px[2] + px[3]);
    float cy = 0.25f * (py[0] + py[1] + py[2] + py[3]);

    // ---- ceiling z ------------------------------------------------------
    float cz = 0.0f;
#pragma unroll
    for (int i = 0; i < 4; i++) {
        float cn = fsqrt_fast(px[i] * px[i] + py[i] * py[i]);
        cz += cn * __tanf(tv[i] * (-0.5f * PIf));
    }
    cz *= 0.25f;

    // ---- centered points + angle argsort (stable, atan2-free) -----------
    float fxx[4], fxy[4];
    float ka[4], kb[4];                 // comparator keys (a = fxx, b = fxy + 1e-12)
#pragma unroll
    for (int i = 0; i < 4; i++) {
        fxx[i] = px[i] - cx;
        fxy[i] = py[i] - cy;
        ka[i] = fxx[i];
        kb[i] = fxy[i] + 1e-12f;
    }
    int idx[4] = {0, 1, 2, 3};
#pragma unroll
    for (int pass = 0; pass < 3; pass++) {
#pragma unroll
        for (int j = 0; j < 3 - pass; j++) {
            if (angLess(ka[j + 1], kb[j + 1], ka[j], kb[j])) {   // strict: ang[j] > ang[j+1]
                float t;
                t = ka[j]; ka[j] = ka[j + 1]; ka[j + 1] = t;
                t = kb[j]; kb[j] = kb[j + 1]; kb[j + 1] = t;
                int ti = idx[j]; idx[j] = idx[j + 1]; idx[j + 1] = ti;
            }
        }
    }

    // ---- destination square corners: axes[i] = cuboid_axes[idx[i]] ------
    float ddx[4], ddy[4];
#pragma unroll
    for (int i = 0; i < 4; i++) {
        int k = idx[i];
        ddx[i] = __ldg(&cax[2 * k]);
        ddy[i] = __ldg(&cax[2 * k + 1]);
    }

    // ---- homography H: fx -> axes, projective-basis closed form ---------
    float s0 = det3(fxx[3], fxy[3], fxx[1], fxy[1], fxx[2], fxy[2]);
    float s1 = det3(fxx[0], fxy[0], fxx[3], fxy[3], fxx[2], fxy[2]);
    float s2 = det3(fxx[0], fxy[0], fxx[1], fxy[1], fxx[3], fxy[3]);
    float t0 = det3(ddx[3], ddy[3], ddx[1], ddy[1], ddx[2], ddy[2]);
    float t1 = det3(ddx[0], ddy[0], ddx[3], ddy[3], ddx[2], ddy[2]);
    float t2 = det3(ddx[0], ddy[0], ddx[1], ddy[1], ddx[3], ddy[3]);

    // adj(H_src): rows = cross products of H_src columns Cj = sj*(xj,yj,1)
    float a0 = s1 * s2 * (fxy[1] - fxy[2]);
    float b0 = s1 * s2 * (fxx[2] - fxx[1]);
    float c0 = s1 * s2 * (fxx[1] * fxy[2] - fxx[2] * fxy[1]);
    float a1 = s2 * s0 * (fxy[2] - fxy[0]);
    float b1 = s2 * s0 * (fxx[0] - fxx[2]);
    float c1 = s2 * s0 * (fxx[2] * fxy[0] - fxx[0] * fxy[2]);
    float a2 = s0 * s1 * (fxy[0] - fxy[1]);
    float b2 = s0 * s1 * (fxx[1] - fxx[0]);
    float c2 = s0 * s1 * (fxx[0] * fxy[1] - fxx[1] * fxy[0]);

    // H = H_dst * adj(H_src); H_dst columns Dj = tj*(dxj,dyj,1)
    float w0 = t0 * ddx[0], w1 = t1 * ddx[1], w2 = t2 * ddx[2];
    float H00 = w0 * a0 + w1 * a1 + w2 * a2;
    float H01 = w0 * b0 + w1 * b1 + w2 * b2;
    float H02 = w0 * c0 + w1 * c1 + w2 * c2;
    w0 = t0 * ddy[0]; w1 = t1 * ddy[1]; w2 = t2 * ddy[2];
    float H10 = w0 * a0 + w1 * a1 + w2 * a2;
    float H11 = w0 * b0 + w1 * b1 + w2 * b2;
    float H12 = w0 * c0 + w1 * c1 + w2 * c2;
    float H20 = t0 * a0 + t1 * a1 + t2 * a2;
    float H21 = t0 * b0 + t1 * b1 + t2 * b2;
    float H22 = t0 * c0 + t1 * c1 + t2 * c2;

    // ---- apply H, rescale, re-center ------------------------------------
    float rx[4], ry[4];
#pragma unroll
    for (int i = 0; i < 4; i++) {
        float wz = H20 * fxx[i] + H21 * fxy[i] + H22;
        float inv = __fdividef(1.0f, wz);
        float X = (H00 * fxx[i] + H01 * fxy[i] + H02) * inv;
        float Y = (H10 * fxx[i] + H11 * fxy[i] + H12) * inv;
        rx[i] = X * sc_x + cx;
        ry[i] = Y * sc_y + cy;
    }

    // ---- Procrustes (closed-form 2x2 Kabsch) ----------------------------
    float rcx = 0.25f * (rx[0] + rx[1] + rx[2] + rx[3]);
    float rcy = 0.25f * (ry[0] + ry[1] + ry[2] + ry[3]);

    float K00 = 0.f, K01 = 0.f, K10 = 0.f, K11 = 0.f, var = 0.f;
#pragma unroll
    for (int i = 0; i < 4; i++) {
        float c1x = rx[i] - rcx;
        float c1y = ry[i] - rcy;
        int k = idx[i];
        float ox = sel4(k, px[0], px[1], px[2], px[3]);
        float oy = sel4(k, py[0], py[1], py[2], py[3]);
        float c2x = ox - rcx;
        float c2y = oy - rcy;
        var += c1x * c1x + c1y * c1y;
        K00 += c1x * c2x;
        K01 += c1x * c2y;
        K10 += c1y * c2x;
        K11 += c1y * c2y;
    }
    float aa = K00 + K11;
    float bb = K01 - K10;
    float q  = aa * aa + bb * bb;
    float inv_r = rsqrtf(q);
    float cth = aa * inv_r;
    float sth = bb * inv_r;
    float scl = __fdividef(q * inv_r, var);   // rr / var

    float Rx[4], Ry[4];
#pragma unroll
    for (int i = 0; i < 4; i++) {
        float vx = rx[i] - rcx;
        float vy = ry[i] - rcy;
        Rx[i] = rcx + scl * (cth * vx - sth * vy);
        Ry[i] = rcy + scl * (sth * vx + cth * vy);
    }

    // ---- write outputs (12 floats each = 3x float4) ---------------------
    float4* ot = reinterpret_cast<float4*>(out_top) + (size_t)b * 3;
    float4* ob = reinterpret_cast<float4*>(out_bot) + (size_t)b * 3;
    ot[0] = make_float4(Rx[0], Ry[0], cz, Rx[1]);
    ot[1] = make_float4(Ry[1], cz, Rx[2], Ry[2]);
    ot[2] = make_float4(cz, Rx[3], Ry[3], cz);
    ob[0] = make_float4(Rx[0], Ry[0], FLOOR_Zf, Rx[1]);
    ob[1] = make_float4(Ry[1], FLOOR_Zf, Rx[2], Ry[2]);
    ob[2] = make_float4(FLOOR_Zf, Rx[3], Ry[3], FLOOR_Zf);
}

extern "C" void kernel_launch(void* const* d_in, const int* in_sizes, int n_in,
                              void* d_out, int out_size)
{
    int B = in_sizes[0] / 8;  // top_corners is (B,4,2)
    const float4* topc = (const float4*)d_in[0];
    const float4* botc = (const float4*)d_in[1];
    const float*  cax  = (const float*)d_in[2];
    float* out_top = (float*)d_out;
    float* out_bot = out_top + (size_t)B * 12;

    int threads = 256;
    int blocks = (B + threads - 1) / threads;
    cuboid_kernel<<<blocks, threads>>>(topc, botc, cax, out_top, out_bot, B);
}